// round 17
// baseline (speedup 1.0000x reference)
#include <cuda_runtime.h>
#include <cuda_fp16.h>
#include <cstdint>
#include <cstddef>

#define CKDIM 64
#define K2    128
#define NP    4096
#define NN    8192
#define NV    1024
#define NBLK  64

// ---------------- scratch ----------------
__device__ __half g_SH[(size_t)NP * NN];           // E^T[p][n] fp16 (67 MB, L2-resident)
__device__ __half g_QH[(size_t)NP * K2];           // [p][k] fp16 [2qk*qe; -qe]
__device__ __half g_MH[(size_t)NN * K2];           // [n][k] fp16 [mk; mk^2]
__device__ __half g_MVh[(size_t)NV * NN];          // fp16 mv (16 MB, K-major)
__device__ float g_bsq[NP];
__device__ float g_msn[NN];
__device__ float g_part[(size_t)NBLK * NP];
__device__ float g_rinv[NP];

__device__ __forceinline__ void cp16(uint32_t dst, const void* src) {
    asm volatile("cp.async.cg.shared.global [%0], [%1], 16;\n" :: "r"(dst), "l"(src));
}
__device__ __forceinline__ uint32_t smem_u32(const void* p) {
    return (uint32_t)__cvta_generic_to_shared(p);
}
__device__ __forceinline__ void ldsm4(uint32_t* r, uint32_t addr) {
    asm volatile("ldmatrix.sync.aligned.m8n8.x4.shared.b16 {%0,%1,%2,%3}, [%4];"
                 : "=r"(r[0]), "=r"(r[1]), "=r"(r[2]), "=r"(r[3]) : "r"(addr));
}
#define MMA_F16U(acc, a, b0, b1)                                                     \
    asm volatile(                                                                    \
        "mma.sync.aligned.m16n8k16.row.col.f32.f16.f16.f32 "                         \
        "{%0,%1,%2,%3}, {%4,%5,%6,%7}, {%8,%9}, {%0,%1,%2,%3};\n"                    \
        : "+f"((acc)[0]), "+f"((acc)[1]), "+f"((acc)[2]), "+f"((acc)[3])             \
        : "r"((a)[0]), "r"((a)[1]), "r"((a)[2]), "r"((a)[3]), "r"(b0), "r"(b1))
#define CP_COMMIT()  asm volatile("cp.async.commit_group;\n" ::)
#define CP_WAIT(N)   asm volatile("cp.async.wait_group %0;\n" :: "n"(N))

// row stride for all GEMM smem tiles: 64 fp16 data + 8 pad = 144 B
#define RS    144
#define TSZ   (128 * RS)      // 18432 B per operand tile

// ---------------- prep kernels (32 rows x 8 chunk groups) ------------
__global__ void prep_q_kernel(const float* __restrict__ qk, const float* __restrict__ qe) {
    __shared__ float red[8][33];
    const int lane = threadIdx.x;
    const int cg   = threadIdx.y;
    const int p = blockIdx.x * 32 + lane;
    float bsq = 0.f;
    __align__(16) __half hq[8], he[8];
#pragma unroll
    for (int u = 0; u < 8; ++u) {
        int c = cg * 8 + u;
        float k = qk[c * NP + p];
        float e = qe[c * NP + p];
        hq[u] = __float2half_rn(2.f * k * e);
        he[u] = __float2half_rn(-e);
        bsq = fmaf(e * k, k, bsq);
    }
    *(uint4*)&g_QH[(size_t)p * K2 + cg * 8]      = *(uint4*)hq;
    *(uint4*)&g_QH[(size_t)p * K2 + 64 + cg * 8] = *(uint4*)he;
    red[cg][lane] = bsq;
    __syncthreads();
    if (cg == 0) {
        float s = bsq;
#pragma unroll
        for (int y = 1; y < 8; ++y) s += red[y][lane];
        g_bsq[p] = s;
    }
}

__global__ void prep_m_kernel(const float* __restrict__ mk, const float* __restrict__ ms) {
    const int lane = threadIdx.x;
    const int cg   = threadIdx.y;
    const int n = blockIdx.x * 32 + lane;
    __align__(16) __half hv[8], hv2[8];
#pragma unroll
    for (int u = 0; u < 8; ++u) {
        int c = cg * 8 + u;
        float v = mk[c * NN + n];
        hv[u]  = __float2half_rn(v);
        hv2[u] = __float2half_rn(v * v);
    }
    *(uint4*)&g_MH[(size_t)n * K2 + cg * 8]      = *(uint4*)hv;
    *(uint4*)&g_MH[(size_t)n * K2 + 64 + cg * 8] = *(uint4*)hv2;
    if (cg == 0) g_msn[n] = ms[n] * 0.125f;
}

__global__ void prep_mv_kernel(const float* __restrict__ mv) {
    size_t i = (size_t)blockIdx.x * blockDim.x + threadIdx.x;   // float4 index
    float4 v = ((const float4*)mv)[i];
    __half2 h01 = __floats2half2_rn(v.x, v.y);
    __half2 h23 = __floats2half2_rn(v.z, v.w);
    uint2 pk;
    pk.x = *(uint32_t*)&h01;
    pk.y = *(uint32_t*)&h23;
    ((uint2*)g_MVh)[i] = pk;
}

// ---------------- sim kernel: fp16 m16n8k16, 2 n-tiles per CTA, resident Q -------
// grid (32, 16) per p-half: x = n-pair (256 n), y = p-tile within half.
#define SSMEM (5 * TSZ)

__global__ __launch_bounds__(256, 2) void sim_kernel(int py0) {
    extern __shared__ __half sh[];
    __shared__ float red[2][128];

    const int tid  = threadIdx.x;
    const int bNp  = (py0 + blockIdx.y) * 128;   // p offset
    const int nb0  = blockIdx.x * 256;           // first n tile
    const int warp = tid >> 5;
    const int lane = tid & 31;
    const int wm = (warp & 3) * 32;
    const int nw = warp >> 2;
    const int wn = nw * 64;
    const int g  = lane >> 2;
    const int tg = lane & 3;
    const uint32_t sbase = smem_u32(sh);
    const uint32_t QB0 = sbase;
    const uint32_t QB1 = sbase + TSZ;
    const uint32_t MB[3] = {sbase + 2 * TSZ, sbase + 3 * TSZ, sbase + 4 * TSZ};
    char* stg = (char*)sh + 3 * TSZ;             // M1 reused as staging

    uint32_t aoff[2];
#pragma unroll
    for (int i = 0; i < 2; ++i)
        aoff[i] = (uint32_t)(wm + 16 * i + (lane & 15)) * RS + ((lane >> 4) & 1) * 16;
    uint32_t boff[4];
#pragma unroll
    for (int jp = 0; jp < 4; ++jp)
        boff[jp] = (uint32_t)(wn + 16 * jp + ((lane >> 4) & 1) * 8 + (lane & 7)) * RS +
                   ((lane >> 3) & 1) * 16;

    float acc[2][8][4];

    auto load_q = [&](int kt) {
        uint32_t ab = sbase + kt * TSZ;
#pragma unroll
        for (int s = 0; s < 4; ++s) {
            int id = tid + s * 256;
            int r = id >> 3, c = id & 7;
            cp16(ab + r * RS + c * 16, &g_QH[(size_t)(bNp + r) * K2 + kt * 64 + c * 8]);
        }
    };
    auto load_m = [&](int nt, int kt, int buf) {
        uint32_t mb = MB[buf];
        int bNn = nb0 + nt * 128;
#pragma unroll
        for (int s = 0; s < 4; ++s) {
            int id = tid + s * 256;
            int r = id >> 3, c = id & 7;
            cp16(mb + r * RS + c * 16, &g_MH[(size_t)(bNn + r) * K2 + kt * 64 + c * 8]);
        }
    };
    auto mma_step = [&](uint32_t qb, uint32_t mb) {
#pragma unroll
        for (int ks = 0; ks < 4; ++ks) {
            const uint32_t kb = ks * 32;
            uint32_t af[2][4], bf[4][4];
            ldsm4(af[0], qb + aoff[0] + kb);
            ldsm4(af[1], qb + aoff[1] + kb);
            ldsm4(bf[0], mb + boff[0] + kb);
            ldsm4(bf[1], mb + boff[1] + kb);
            MMA_F16U(acc[0][0], af[0], bf[0][0], bf[0][1]);
            MMA_F16U(acc[0][1], af[0], bf[0][2], bf[0][3]);
            ldsm4(bf[2], mb + boff[2] + kb);
            MMA_F16U(acc[1][0], af[1], bf[0][0], bf[0][1]);
            MMA_F16U(acc[1][1], af[1], bf[0][2], bf[0][3]);
            ldsm4(bf[3], mb + boff[3] + kb);
            MMA_F16U(acc[0][2], af[0], bf[1][0], bf[1][1]);
            MMA_F16U(acc[0][3], af[0], bf[1][2], bf[1][3]);
            MMA_F16U(acc[1][2], af[1], bf[1][0], bf[1][1]);
            MMA_F16U(acc[1][3], af[1], bf[1][2], bf[1][3]);
#pragma unroll
            for (int i = 0; i < 2; ++i)
#pragma unroll
                for (int jp = 2; jp < 4; ++jp) {
                    MMA_F16U(acc[i][2 * jp],     af[i], bf[jp][0], bf[jp][1]);
                    MMA_F16U(acc[i][2 * jp + 1], af[i], bf[jp][2], bf[jp][3]);
                }
        }
    };

    float bsqr[2][2];
#pragma unroll
    for (int i = 0; i < 2; ++i) {
        int r0 = bNp + wm + 16 * i + g;
        bsqr[i][0] = g_bsq[r0];
        bsqr[i][1] = g_bsq[r0 + 8];
    }

    auto epilogue = [&](int nt) {
        int bNn = nb0 + nt * 128;
        float msv[8][2];
#pragma unroll
        for (int j = 0; j < 8; ++j) {
            int c0 = bNn + wn + 8 * j + 2 * tg;
            msv[j][0] = g_msn[c0];
            msv[j][1] = g_msn[c0 + 1];
        }
        float rsum[2][2];
        rsum[0][0] = rsum[0][1] = rsum[1][0] = rsum[1][1] = 0.f;

        __syncthreads();
#pragma unroll
        for (int half = 0; half < 2; ++half) {
            if (nw == half) {
#pragma unroll
                for (int i = 0; i < 2; ++i) {
                    int srow = wm + 16 * i + g;
#pragma unroll
                    for (int j = 0; j < 8; ++j) {
                        __half h0 = __float2half_rn(__expf(msv[j][0] * (acc[i][j][0] - bsqr[i][0])));
                        __half h1 = __float2half_rn(__expf(msv[j][1] * (acc[i][j][1] - bsqr[i][0])));
                        __half h2 = __float2half_rn(__expf(msv[j][0] * (acc[i][j][2] - bsqr[i][1])));
                        __half h3 = __float2half_rn(__expf(msv[j][1] * (acc[i][j][3] - bsqr[i][1])));
                        int scol = 8 * j + 2 * tg;
                        *(__half2*)(stg + srow * RS + scol * 2)       = __halves2half2(h0, h1);
                        *(__half2*)(stg + (srow + 8) * RS + scol * 2) = __halves2half2(h2, h3);
                        rsum[i][0] += __half2float(h0) + __half2float(h1);
                        rsum[i][1] += __half2float(h2) + __half2float(h3);
                    }
                }
            }
            __syncthreads();
#pragma unroll
            for (int s = 0; s < 4; ++s) {
                int id = tid + s * 256;
                int row = id >> 3, c = id & 7;
                uint4 v = *(const uint4*)(stg + row * RS + c * 16);
                *(uint4*)&g_SH[(size_t)(bNp + row) * NN + bNn + half * 64 + c * 8] = v;
            }
            __syncthreads();
        }

#pragma unroll
        for (int i = 0; i < 2; ++i)
#pragma unroll
            for (int d = 0; d < 2; ++d) {
                float s = rsum[i][d];
                s += __shfl_xor_sync(0xffffffffu, s, 1);
                s += __shfl_xor_sync(0xffffffffu, s, 2);
                if (tg == 0) red[nw][wm + 16 * i + 8 * d + g] = s;
            }
        __syncthreads();
        if (tid < 128)
            g_part[(size_t)(blockIdx.x * 2 + nt) * NP + bNp + tid] =
                red[0][tid] + red[1][tid];
    };

    auto zacc = [&]() {
#pragma unroll
        for (int i = 0; i < 2; ++i)
#pragma unroll
            for (int j = 0; j < 8; ++j)
#pragma unroll
                for (int r = 0; r < 4; ++r) acc[i][j][r] = 0.f;
    };

    load_q(0); load_q(1); load_m(0, 0, 0); CP_COMMIT();
    load_m(0, 1, 1); CP_COMMIT();

    CP_WAIT(1); __syncthreads();
    load_m(1, 0, 2); CP_COMMIT();
    zacc();
    mma_step(QB0, MB[0]);
    CP_WAIT(1); __syncthreads();
    load_m(1, 1, 0); CP_COMMIT();
    mma_step(QB1, MB[1]);
    epilogue(0);
    CP_WAIT(1); __syncthreads();
    zacc();
    mma_step(QB0, MB[2]);
    CP_WAIT(0); __syncthreads();
    mma_step(QB1, MB[0]);
    epilogue(1);
}

// ---------------- rinv (p-sliced) ----------------
__global__ void rinv_kernel(int p0) {
    __shared__ float red[8][33];
    const int lane = threadIdx.x;
    const int bg   = threadIdx.y;
    const int p = p0 + blockIdx.x * 32 + lane;
    float s = 0.f;
#pragma unroll
    for (int u = 0; u < 8; ++u)
        s += g_part[(size_t)(bg * 8 + u) * NP + p];
    red[bg][lane] = s;
    __syncthreads();
    if (bg == 0) {
#pragma unroll
        for (int y = 1; y < 8; ++y) s += red[y][lane];
        g_rinv[p] = 1.0f / s;
    }
}

// ---------------- readout GEMM: fp16 m16n8k16 + LDSM, 4 warps x 64x64 tiles ------
#define OBK   64
#define ONKT  (NN / OBK)        // 128
#define OSTG  (2 * TSZ)         // 36864 B per stage
#define OSMEM (3 * OSTG)        // 110592 B

__global__ __launch_bounds__(128, 2) void out_gemm_kernel(float* __restrict__ out, int pg0) {
    extern __shared__ __half Sh[];
    const int tid  = threadIdx.x;
    const int warp = tid >> 5;
    const int lane = tid & 31;
    const int bM = blockIdx.x * 128;
    const int bN = (pg0 + blockIdx.y) * 128;
    const int wm = (warp & 1) * 64;
    const int wn = (warp >> 1) * 64;
    const int g  = lane >> 2;
    const int tg = lane & 3;
    const uint32_t sbase = smem_u32(Sh);

    uint32_t aoff[4];
#pragma unroll
    for (int i = 0; i < 4; ++i)
        aoff[i] = (uint32_t)(wm + 16 * i + (lane & 15)) * RS + ((lane >> 4) & 1) * 16;
    uint32_t boff[4];
#pragma unroll
    for (int jp = 0; jp < 4; ++jp)
        boff[jp] = TSZ +
                   (uint32_t)(wn + 16 * jp + ((lane >> 4) & 1) * 8 + (lane & 7)) * RS +
                   ((lane >> 3) & 1) * 16;

    float acc[4][8][4];
#pragma unroll
    for (int i = 0; i < 4; ++i)
#pragma unroll
        for (int j = 0; j < 8; ++j)
#pragma unroll
            for (int r = 0; r < 4; ++r) acc[i][j][r] = 0.f;

    auto load_A_half = [&](int kt, int st, int h) {
        uint32_t ab = sbase + st * OSTG;
#pragma unroll
        for (int s = 0; s < 4; ++s) {
            int id = tid + (h * 4 + s) * 128;
            int r = id >> 3, c = id & 7;
            cp16(ab + r * RS + c * 16, &g_MVh[(size_t)(bM + r) * NN + kt * OBK + c * 8]);
        }
    };
    auto load_B_half = [&](int kt, int st, int h) {
        uint32_t bb = sbase + st * OSTG + TSZ;
#pragma unroll
        for (int s = 0; s < 4; ++s) {
            int id = tid + (h * 4 + s) * 128;
            int r = id >> 3, c = id & 7;
            cp16(bb + r * RS + c * 16, &g_SH[(size_t)(bN + r) * NN + kt * OBK + c * 8]);
        }
    };

    load_A_half(0, 0, 0); load_A_half(0, 0, 1);
    load_B_half(0, 0, 0); load_B_half(0, 0, 1); CP_COMMIT();
    load_A_half(1, 1, 0); load_A_half(1, 1, 1);
    load_B_half(1, 1, 0); load_B_half(1, 1, 1); CP_COMMIT();

    for (int kt = 0; kt < ONKT; ++kt) {
        if (kt + 1 < ONKT) CP_WAIT(1);
        else               CP_WAIT(0);
        __syncthreads();

        const uint32_t stb = sbase + (kt % 3) * OSTG;
        const bool pf = (kt + 2 < ONKT);
        const int pfs = (kt + 2) % 3;

#pragma unroll
        for (int ks = 0; ks < 4; ++ks) {
            const uint32_t kb = ks * 32;
            uint32_t af[4][4], bf[4][4];
            ldsm4(af[0], stb + aoff[0] + kb);
            ldsm4(af[1], stb + aoff[1] + kb);
            ldsm4(af[2], stb + aoff[2] + kb);
            ldsm4(af[3], stb + aoff[3] + kb);
            ldsm4(bf[0], stb + boff[0] + kb);
            ldsm4(bf[1], stb + boff[1] + kb);
            MMA_F16U(acc[0][0], af[0], bf[0][0], bf[0][1]);
            MMA_F16U(acc[0][1], af[0], bf[0][2], bf[0][3]);
            MMA_F16U(acc[1][0], af[1], bf[0][0], bf[0][1]);
            MMA_F16U(acc[1][1], af[1], bf[0][2], bf[0][3]);
            ldsm4(bf[2], stb + boff[2] + kb);
            MMA_F16U(acc[2][0], af[2], bf[0][0], bf[0][1]);
            MMA_F16U(acc[2][1], af[2], bf[0][2], bf[0][3]);
            MMA_F16U(acc[3][0], af[3], bf[0][0], bf[0][1]);
            MMA_F16U(acc[3][1], af[3], bf[0][2], bf[0][3]);
            ldsm4(bf[3], stb + boff[3] + kb);
#pragma unroll
            for (int i = 0; i < 4; ++i) {
                MMA_F16U(acc[i][2], af[i], bf[1][0], bf[1][1]);
                MMA_F16U(acc[i][3], af[i], bf[1][2], bf[1][3]);
            }
#pragma unroll
            for (int i = 0; i < 4; ++i)
#pragma unroll
                for (int jp = 2; jp < 4; ++jp) {
                    MMA_F16U(acc[i][2 * jp],     af[i], bf[jp][0], bf[jp][1]);
                    MMA_F16U(acc[i][2 * jp + 1], af[i], bf[jp][2], bf[jp][3]);
                }
            if (pf) {
                if (ks == 0)      load_A_half(kt + 2, pfs, 0);
                else if (ks == 1) load_A_half(kt + 2, pfs, 1);
                else if (ks == 2) load_B_half(kt + 2, pfs, 0);
                else            { load_B_half(kt + 2, pfs, 1); CP_COMMIT(); }
            }
        }
    }

#pragma unroll
    for (int j = 0; j < 8; ++j) {
        int c = bN + wn + 8 * j + 2 * tg;
        float r0 = g_rinv[c];
        float r1 = g_rinv[c + 1];
#pragma unroll
        for (int i = 0; i < 4; ++i) {
            int rr = bM + wm + 16 * i + g;
            *(float2*)&out[(size_t)rr * NP + c] =
                make_float2(acc[i][j][0] * r0, acc[i][j][1] * r1);
            *(float2*)&out[(size_t)(rr + 8) * NP + c] =
                make_float2(acc[i][j][2] * r0, acc[i][j][3] * r1);
        }
    }
}

// ---------------- launch: 2-group software pipeline across two streams ----------
extern "C" void kernel_launch(void* const* d_in, const int* in_sizes, int n_in,
                              void* d_out, int out_size) {
    const float* qk = (const float*)d_in[0];
    const float* qe = (const float*)d_in[1];
    const float* mk = (const float*)d_in[2];
    const float* ms = (const float*)d_in[3];
    const float* mv = (const float*)d_in[4];
    float* out = (float*)d_out;

    cudaFuncSetAttribute(sim_kernel, cudaFuncAttributeMaxDynamicSharedMemorySize, SSMEM);
    cudaFuncSetAttribute(out_gemm_kernel, cudaFuncAttributeMaxDynamicSharedMemorySize, OSMEM);

    // side stream + events (host-side resources; created once, never destroyed)
    static cudaStream_t sB = nullptr;
    static cudaEvent_t evRoot, evA, evB, evDone;
    if (sB == nullptr) {
        cudaStreamCreateWithFlags(&sB, cudaStreamNonBlocking);
        cudaEventCreateWithFlags(&evRoot, cudaEventDisableTiming);
        cudaEventCreateWithFlags(&evA,    cudaEventDisableTiming);
        cudaEventCreateWithFlags(&evB,    cudaEventDisableTiming);
        cudaEventCreateWithFlags(&evDone, cudaEventDisableTiming);
    }

    // fork: sB joins the capture DAG via evRoot
    cudaEventRecord(evRoot, 0);
    cudaStreamWaitEvent(sB, evRoot, 0);
    prep_mv_kernel<<<(NV * NN / 4) / 256, 256, 0, sB>>>(mv);

    // main stream: prep + sim/rinv for p-half 0
    prep_q_kernel<<<NP / 32, dim3(32, 8)>>>(qk, qe);
    prep_m_kernel<<<NN / 32, dim3(32, 8)>>>(mk, ms);
    sim_kernel<<<dim3(32, 16), 256, SSMEM>>>(0);
    rinv_kernel<<<64, dim3(32, 8)>>>(0);
    cudaEventRecord(evA, 0);

    // side stream: out for half 0 while main does sim half 1
    cudaStreamWaitEvent(sB, evA, 0);
    out_gemm_kernel<<<dim3(NV / 128, 16), 128, OSMEM, sB>>>(out, 0);

    sim_kernel<<<dim3(32, 16), 256, SSMEM>>>(16);
    rinv_kernel<<<64, dim3(32, 8)>>>(2048);
    cudaEventRecord(evB, 0);

    cudaStreamWaitEvent(sB, evB, 0);
    out_gemm_kernel<<<dim3(NV / 128, 16), 128, OSMEM, sB>>>(out, 16);
    cudaEventRecord(evDone, sB);

    // join back to the capture stream
    cudaStreamWaitEvent(0, evDone, 0);
}